// round 2
// baseline (speedup 1.0000x reference)
#include <cuda_runtime.h>
#include <math.h>

#define DIM     1024
#define HIDDEN  2560
#define NEXP    4
#define NTOK    8192
#define CAP     8192

#define BM 64
#define BN 128
#define BK 16

// ---- static scratch (no allocation allowed) ----
__device__ int   g_cnt[NEXP];
__device__ int   g_list[NEXP * CAP];
__device__ float g_wt[NEXP * CAP];
__device__ float g_h[(size_t)NEXP * CAP * HIDDEN];   // ~335 MB, compacted per expert

// ---------------- init ----------------
__global__ void k_init() {
    if (threadIdx.x < NEXP) g_cnt[threadIdx.x] = 0;
}

// ---------------- gating: one warp per token ----------------
__global__ void __launch_bounds__(256) k_gate(const float* __restrict__ x,
                                              const float* __restrict__ gw) {
    int warp = (blockIdx.x * blockDim.x + threadIdx.x) >> 5;
    int lane = threadIdx.x & 31;
    if (warp >= NTOK) return;
    const float* xr = x + (size_t)warp * DIM;

    float acc[NEXP] = {0.f, 0.f, 0.f, 0.f};
    for (int i = lane; i < DIM; i += 32) {
        float xv = xr[i];
#pragma unroll
        for (int e = 0; e < NEXP; e++) acc[e] += xv * gw[e * DIM + i];
    }
#pragma unroll
    for (int o = 16; o > 0; o >>= 1) {
#pragma unroll
        for (int e = 0; e < NEXP; e++)
            acc[e] += __shfl_xor_sync(0xffffffffu, acc[e], o);
    }
    if (lane == 0) {
        float m = acc[0];
#pragma unroll
        for (int e = 1; e < NEXP; e++) m = fmaxf(m, acc[e]);
        float p[NEXP], s = 0.f;
#pragma unroll
        for (int e = 0; e < NEXP; e++) { p[e] = expf(acc[e] - m); s += p[e]; }
        float inv_s = 1.f / s;
#pragma unroll
        for (int e = 0; e < NEXP; e++) p[e] *= inv_s;

        // top-2 (earliest index wins ties, matching jax top_k)
        int i0 = 0;
#pragma unroll
        for (int e = 1; e < NEXP; e++) if (p[e] > p[i0]) i0 = e;
        int i1 = -1;
#pragma unroll
        for (int e = 0; e < NEXP; e++)
            if (e != i0 && (i1 < 0 || p[e] > p[i1])) i1 = e;

        float w0 = p[i0], w1 = p[i1];
        float inv = 1.f / (w0 + w1);
        w0 *= inv; w1 *= inv;

        int q0 = atomicAdd(&g_cnt[i0], 1);
        g_list[i0 * CAP + q0] = warp; g_wt[i0 * CAP + q0] = w0;
        int q1 = atomicAdd(&g_cnt[i1], 1);
        g_list[i1 * CAP + q1] = warp; g_wt[i1 * CAP + q1] = w1;
    }
}

// ---------------- GEMM1: h = silu(Xg W1^T) * (Xg W3^T), per expert ----------------
// grid: (HIDDEN/BN, CAP/BM, NEXP), block 256
__global__ void __launch_bounds__(256, 2) k_ffn1(const float* __restrict__ x,
                                                 const float* __restrict__ w1,
                                                 const float* __restrict__ w3) {
    int e  = blockIdx.z;
    int m0 = blockIdx.y * BM;
    int h0 = blockIdx.x * BN;
    int cnt = g_cnt[e];
    if (m0 >= cnt) return;

    __shared__ float As[BK][BM + 4];
    __shared__ float B1[BK][BN + 4];
    __shared__ float B3[BK][BN + 4];
    __shared__ int   rows[BM];

    int tid = threadIdx.x;
    if (tid < BM) {
        int m = m0 + tid;
        rows[tid] = (m < cnt) ? g_list[e * CAP + m] : -1;
    }
    __syncthreads();

    int a_r = tid >> 2;             // 0..63
    int a_k = (tid & 3) * 4;        // 0,4,8,12
    int b_r = tid >> 1;             // 0..127
    int b_k = (tid & 1) * 8;        // 0,8

    int arow = rows[a_r];
    const float* xp  = x  + ((arow >= 0) ? ((size_t)arow * DIM + a_k) : 0);
    const float* w1p = w1 + ((size_t)e * HIDDEN + h0 + b_r) * DIM + b_k;
    const float* w3p = w3 + ((size_t)e * HIDDEN + h0 + b_r) * DIM + b_k;

    int ty = tid >> 4;   // m group 0..15
    int tx = tid & 15;   // h group 0..15

    float acc1[4][8], acc3[4][8];
#pragma unroll
    for (int i = 0; i < 4; i++)
#pragma unroll
        for (int j = 0; j < 8; j++) { acc1[i][j] = 0.f; acc3[i][j] = 0.f; }

    for (int k0 = 0; k0 < DIM; k0 += BK) {
        float4 av = make_float4(0.f, 0.f, 0.f, 0.f);
        if (arow >= 0) av = *(const float4*)(xp + k0);
        float4 b1a = *(const float4*)(w1p + k0);
        float4 b1b = *(const float4*)(w1p + k0 + 4);
        float4 b3a = *(const float4*)(w3p + k0);
        float4 b3b = *(const float4*)(w3p + k0 + 4);

        As[a_k + 0][a_r] = av.x; As[a_k + 1][a_r] = av.y;
        As[a_k + 2][a_r] = av.z; As[a_k + 3][a_r] = av.w;
        B1[b_k + 0][b_r] = b1a.x; B1[b_k + 1][b_r] = b1a.y;
        B1[b_k + 2][b_r] = b1a.z; B1[b_k + 3][b_r] = b1a.w;
        B1[b_k + 4][b_r] = b1b.x; B1[b_k + 5][b_r] = b1b.y;
        B1[b_k + 6][b_r] = b1b.z; B1[b_k + 7][b_r] = b1b.w;
        B3[b_k + 0][b_r] = b3a.x; B3[b_k + 1][b_r] = b3a.y;
        B3[b_k + 2][b_r] = b3a.z; B3[b_k + 3][b_r] = b3a.w;
        B3[b_k + 4][b_r] = b3b.x; B3[b_k + 5][b_r] = b3b.y;
        B3[b_k + 6][b_r] = b3b.z; B3[b_k + 7][b_r] = b3b.w;
        __syncthreads();

#pragma unroll
        for (int kk = 0; kk < BK; kk++) {
            float4 a  = *(const float4*)(&As[kk][ty * 4]);
            float4 p0 = *(const float4*)(&B1[kk][tx * 8]);
            float4 p1 = *(const float4*)(&B1[kk][tx * 8 + 4]);
            float4 q0 = *(const float4*)(&B3[kk][tx * 8]);
            float4 q1 = *(const float4*)(&B3[kk][tx * 8 + 4]);
            float avv[4] = {a.x, a.y, a.z, a.w};
            float b1v[8] = {p0.x, p0.y, p0.z, p0.w, p1.x, p1.y, p1.z, p1.w};
            float b3v[8] = {q0.x, q0.y, q0.z, q0.w, q1.x, q1.y, q1.z, q1.w};
#pragma unroll
            for (int i = 0; i < 4; i++)
#pragma unroll
                for (int j = 0; j < 8; j++) {
                    acc1[i][j] += avv[i] * b1v[j];
                    acc3[i][j] += avv[i] * b3v[j];
                }
        }
        __syncthreads();
    }

    // epilogue: silu(acc1) * acc3 -> compacted h scratch
#pragma unroll
    for (int i = 0; i < 4; i++) {
        int m = m0 + ty * 4 + i;
        if (m < cnt) {
            float* hp = g_h + ((size_t)e * CAP + m) * HIDDEN + h0 + tx * 8;
#pragma unroll
            for (int j = 0; j < 8; j++) {
                float a1 = acc1[i][j];
                float sv = a1 / (1.f + expf(-a1));
                hp[j] = sv * acc3[i][j];
            }
        }
    }
}

// ---------------- GEMM2: out += wt * (h W2^T), per expert ----------------
// grid: (DIM/BN, CAP/BM, NEXP), block 256
__global__ void __launch_bounds__(256, 2) k_ffn2(const float* __restrict__ w2,
                                                 float* __restrict__ out) {
    int e  = blockIdx.z;
    int m0 = blockIdx.y * BM;
    int d0 = blockIdx.x * BN;
    int cnt = g_cnt[e];
    if (m0 >= cnt) return;

    __shared__ float As[BK][BM + 4];
    __shared__ float Bs[BK][BN + 4];

    int tid = threadIdx.x;
    int a_r = tid >> 2;
    int a_k = (tid & 3) * 4;
    int b_r = tid >> 1;
    int b_k = (tid & 1) * 8;

    bool a_ok = (m0 + a_r) < cnt;
    const float* hp  = g_h + ((size_t)e * CAP + m0 + a_r) * HIDDEN + a_k;
    const float* w2p = w2 + ((size_t)e * DIM + d0 + b_r) * HIDDEN + b_k;

    int ty = tid >> 4;
    int tx = tid & 15;

    float acc[4][8];
#pragma unroll
    for (int i = 0; i < 4; i++)
#pragma unroll
        for (int j = 0; j < 8; j++) acc[i][j] = 0.f;

    for (int k0 = 0; k0 < HIDDEN; k0 += BK) {
        float4 av = make_float4(0.f, 0.f, 0.f, 0.f);
        if (a_ok) av = *(const float4*)(hp + k0);
        float4 ba = *(const float4*)(w2p + k0);
        float4 bb = *(const float4*)(w2p + k0 + 4);

        As[a_k + 0][a_r] = av.x; As[a_k + 1][a_r] = av.y;
        As[a_k + 2][a_r] = av.z; As[a_k + 3][a_r] = av.w;
        Bs[b_k + 0][b_r] = ba.x; Bs[b_k + 1][b_r] = ba.y;
        Bs[b_k + 2][b_r] = ba.z; Bs[b_k + 3][b_r] = ba.w;
        Bs[b_k + 4][b_r] = bb.x; Bs[b_k + 5][b_r] = bb.y;
        Bs[b_k + 6][b_r] = bb.z; Bs[b_k + 7][b_r] = bb.w;
        __syncthreads();

#pragma unroll
        for (int kk = 0; kk < BK; kk++) {
            float4 a  = *(const float4*)(&As[kk][ty * 4]);
            float4 p0 = *(const float4*)(&Bs[kk][tx * 8]);
            float4 p1 = *(const float4*)(&Bs[kk][tx * 8 + 4]);
            float avv[4] = {a.x, a.y, a.z, a.w};
            float bv[8]  = {p0.x, p0.y, p0.z, p0.w, p1.x, p1.y, p1.z, p1.w};
#pragma unroll
            for (int i = 0; i < 4; i++)
#pragma unroll
                for (int j = 0; j < 8; j++)
                    acc[i][j] += avv[i] * bv[j];
        }
        __syncthreads();
    }

#pragma unroll
    for (int i = 0; i < 4; i++) {
        int m = m0 + ty * 4 + i;
        if (m < cnt) {
            int   token = g_list[e * CAP + m];
            float wt    = g_wt[e * CAP + m];
            float* op = out + (size_t)token * DIM + d0 + tx * 8;
#pragma unroll
            for (int j = 0; j < 8; j++)
                atomicAdd(&op[j], wt * acc[i][j]);
        }
    }
}

// ---------------- launch ----------------
extern "C" void kernel_launch(void* const* d_in, const int* in_sizes, int n_in,
                              void* d_out, int out_size) {
    const float* x  = (const float*)d_in[0];
    const float* gw = (const float*)d_in[1];
    const float* w1 = (const float*)d_in[2];
    const float* w2 = (const float*)d_in[3];
    const float* w3 = (const float*)d_in[4];
    float* out = (float*)d_out;

    // zero output (also zeroes aux_loss tail element if present)
    cudaMemsetAsync(out, 0, (size_t)out_size * sizeof(float), 0);

    k_init<<<1, 32>>>();
    k_gate<<<(NTOK * 32) / 256, 256>>>(x, gw);

    dim3 g1(HIDDEN / BN, CAP / BM, NEXP);
    k_ffn1<<<g1, 256>>>(x, w1, w3);

    dim3 g2(DIM / BN, CAP / BM, NEXP);
    k_ffn2<<<g2, 256>>>(w2, out);
}

// round 8
// speedup vs baseline: 11.0685x; 11.0685x over previous
#include <cuda_runtime.h>
#include <cuda_fp16.h>
#include <math.h>
#include <stdint.h>

#define DIM     1024
#define HIDDEN  2560
#define NEXP    4
#define NTOK    8192
#define CAP     8192

#define TM  128
#define TN  128
#define BK  32
#define PAD 40          // halves per smem row (32 data + 8 pad) -> conflict-free ldmatrix

// ---- static scratch (no allocation allowed) ----
__device__ int    g_cnt[NEXP];
__device__ int    g_list[NEXP * CAP];
__device__ int    g_slot[NTOK * 2];
__device__ float  g_cw[NTOK * 2];
__device__ __half g_h[(size_t)NEXP * CAP * HIDDEN];   // compacted SwiGLU output, fp16
__device__ float  g_y[(size_t)NEXP * CAP * DIM];      // compacted GEMM2 output, fp32

// ------------------------------------------------------------------
// helpers
// ------------------------------------------------------------------
__device__ __forceinline__ uint32_t s2u(const void* p) {
    uint32_t a;
    asm("{ .reg .u64 t; cvta.to.shared.u64 t, %1; cvt.u32.u64 %0, t; }" : "=r"(a) : "l"(p));
    return a;
}
__device__ __forceinline__ void ldm4(uint32_t (&r)[4], uint32_t addr) {
    asm volatile("ldmatrix.sync.aligned.m8n8.x4.shared.b16 {%0,%1,%2,%3}, [%4];"
                 : "=r"(r[0]), "=r"(r[1]), "=r"(r[2]), "=r"(r[3]) : "r"(addr));
}
__device__ __forceinline__ void mma16816(float (&d)[4], const uint32_t (&a)[4],
                                         uint32_t b0, uint32_t b1) {
    asm volatile("mma.sync.aligned.m16n8k16.row.col.f32.f16.f16.f32 "
                 "{%0,%1,%2,%3}, {%4,%5,%6,%7}, {%8,%9}, {%0,%1,%2,%3};"
                 : "+f"(d[0]), "+f"(d[1]), "+f"(d[2]), "+f"(d[3])
                 : "r"(a[0]), "r"(a[1]), "r"(a[2]), "r"(a[3]), "r"(b0), "r"(b1));
}
__device__ __forceinline__ uint2 f4h(float4 v) {
    __half2 lo = __floats2half2_rn(v.x, v.y);
    __half2 hi = __floats2half2_rn(v.z, v.w);
    uint2 r;
    r.x = *reinterpret_cast<uint32_t*>(&lo);
    r.y = *reinterpret_cast<uint32_t*>(&hi);
    return r;
}

// ---------------- init + gating ----------------
__global__ void k_init() {
    if (threadIdx.x < NEXP) g_cnt[threadIdx.x] = 0;
}

__global__ void __launch_bounds__(256) k_gate(const float* __restrict__ x,
                                              const float* __restrict__ gw) {
    int warp = (blockIdx.x * blockDim.x + threadIdx.x) >> 5;
    int lane = threadIdx.x & 31;
    if (warp >= NTOK) return;
    const float* xr = x + (size_t)warp * DIM;

    float acc[NEXP] = {0.f, 0.f, 0.f, 0.f};
    for (int i = lane; i < DIM; i += 32) {
        float xv = xr[i];
#pragma unroll
        for (int e = 0; e < NEXP; e++) acc[e] += xv * gw[e * DIM + i];
    }
#pragma unroll
    for (int o = 16; o > 0; o >>= 1) {
#pragma unroll
        for (int e = 0; e < NEXP; e++)
            acc[e] += __shfl_xor_sync(0xffffffffu, acc[e], o);
    }
    if (lane == 0) {
        float m = acc[0];
#pragma unroll
        for (int e = 1; e < NEXP; e++) m = fmaxf(m, acc[e]);
        float p[NEXP], s = 0.f;
#pragma unroll
        for (int e = 0; e < NEXP; e++) { p[e] = expf(acc[e] - m); s += p[e]; }
        float inv_s = 1.f / s;
#pragma unroll
        for (int e = 0; e < NEXP; e++) p[e] *= inv_s;

        int i0 = 0;
#pragma unroll
        for (int e = 1; e < NEXP; e++) if (p[e] > p[i0]) i0 = e;
        int i1 = -1;
#pragma unroll
        for (int e = 0; e < NEXP; e++)
            if (e != i0 && (i1 < 0 || p[e] > p[i1])) i1 = e;

        float w0 = p[i0], w1 = p[i1];
        float inv = 1.f / (w0 + w1);
        w0 *= inv; w1 *= inv;

        int q0 = atomicAdd(&g_cnt[i0], 1);
        g_list[i0 * CAP + q0] = warp;
        g_slot[warp * 2 + 0] = i0 * CAP + q0;
        g_cw[warp * 2 + 0] = w0;
        int q1 = atomicAdd(&g_cnt[i1], 1);
        g_list[i1 * CAP + q1] = warp;
        g_slot[warp * 2 + 1] = i1 * CAP + q1;
        g_cw[warp * 2 + 1] = w1;
    }
}

// ------------------------------------------------------------------
// GEMM1: g_h = fp16( silu(Xg W1^T) * (Xg W3^T) )
// grid (HIDDEN/TN=20, CAP/TM=64, NEXP), block 256 (8 warps = 2M x 4N)
// dyn smem: 2 stages x {A, B1, B3} each 128 x PAD halves
// ------------------------------------------------------------------
#define G1_MAT_H   (128 * PAD)          // halves per matrix (5120)
#define G1_STAGE_H (3 * G1_MAT_H)       // 15360 halves = 30720 B
#define G1_SMEM    (2 * G1_STAGE_H * 2) // 61440 B

__global__ void __launch_bounds__(256) k_ffn1(const float* __restrict__ x,
                                              const float* __restrict__ w1,
                                              const float* __restrict__ w3) {
    int e  = blockIdx.z;
    int m0 = blockIdx.y * TM;
    int h0 = blockIdx.x * TN;
    int cnt = g_cnt[e];
    if (m0 >= cnt) return;

    extern __shared__ __half sm[];
    __shared__ int rows_sh[TM];

    int tid = threadIdx.x;
    int wid = tid >> 5;
    int lane = tid & 31;
    if (tid < TM) {
        int m = m0 + tid;
        rows_sh[tid] = (m < cnt) ? g_list[e * CAP + m] : -1;
    }
    __syncthreads();

    // loader mapping: idx = tid + q*256 -> row = idx>>3, float4-col = idx&7
    const float* pA[4]; const float* pW1[4]; const float* pW3[4];
    uint32_t soff[4];
#pragma unroll
    for (int q = 0; q < 4; q++) {
        int idx = tid + q * 256;
        int row = idx >> 3;
        int c4  = idx & 7;
        soff[q] = row * PAD + c4 * 4;
        int tok = rows_sh[row];
        pA[q]  = (tok >= 0) ? (x + (size_t)tok * DIM + c4 * 4) : (const float*)0;
        pW1[q] = w1 + ((size_t)e * HIDDEN + h0 + row) * DIM + c4 * 4;
        pW3[q] = w3 + ((size_t)e * HIDDEN + h0 + row) * DIM + c4 * 4;
    }

    float acc1[4][4][4], acc3[4][4][4];
#pragma unroll
    for (int i = 0; i < 4; i++)
#pragma unroll
        for (int j = 0; j < 4; j++)
#pragma unroll
            for (int f = 0; f < 4; f++) { acc1[i][j][f] = 0.f; acc3[i][j][f] = 0.f; }

    int wm = (wid >> 2) * 64;
    int wn = (wid & 3) * 32;
    uint32_t smb = s2u(sm);

    uint2 hA[4], hB1[4], hB3[4];

    auto LDREG = [&](int k) {
        int ko = k * BK;
#pragma unroll
        for (int q = 0; q < 4; q++) {
            float4 a = make_float4(0.f, 0.f, 0.f, 0.f);
            if (pA[q]) a = *(const float4*)(pA[q] + ko);
            hA[q]  = f4h(a);
            hB1[q] = f4h(*(const float4*)(pW1[q] + ko));
            hB3[q] = f4h(*(const float4*)(pW3[q] + ko));
        }
    };
    auto STS = [&](int buf) {
        __half* st = sm + buf * G1_STAGE_H;
#pragma unroll
        for (int q = 0; q < 4; q++) {
            *(uint2*)(st + soff[q])                = hA[q];
            *(uint2*)(st + G1_MAT_H + soff[q])     = hB1[q];
            *(uint2*)(st + 2 * G1_MAT_H + soff[q]) = hB3[q];
        }
    };
    auto COMPUTE = [&](int buf) {
        uint32_t sb = smb + buf * G1_STAGE_H * 2;
        uint32_t aAddr = sb + ((wm + (lane & 15)) * PAD + (lane >> 4) * 8) * 2;
        uint32_t bRow  = (wn + ((lane >> 4) << 3) + (lane & 7)) * PAD + ((lane >> 3) & 1) * 8;
#pragma unroll
        for (int ks = 0; ks < 2; ks++) {
            uint32_t a[4][4];
#pragma unroll
            for (int mt = 0; mt < 4; mt++)
                ldm4(a[mt], aAddr + (mt * 16 * PAD + ks * 16) * 2);
            uint32_t b[4], b2[4];
            // B1
            uint32_t bA = sb + G1_MAT_H * 2 + (bRow + ks * 16) * 2;
            ldm4(b,  bA);
            ldm4(b2, bA + 16 * PAD * 2);
#pragma unroll
            for (int mt = 0; mt < 4; mt++) {
                mma16816(acc1[mt][0], a[mt], b[0],  b[1]);
                mma16816(acc1[mt][1], a[mt], b[2],  b[3]);
                mma16816(acc1[mt][2], a[mt], b2[0], b2[1]);
                mma16816(acc1[mt][3], a[mt], b2[2], b2[3]);
            }
            // B3
            uint32_t cA = sb + 2 * G1_MAT_H * 2 + (bRow + ks * 16) * 2;
            ldm4(b,  cA);
            ldm4(b2, cA + 16 * PAD * 2);
#pragma unroll
            for (int mt = 0; mt < 4; mt++) {
                mma16816(acc3[mt][0], a[mt], b[0],  b[1]);
                mma16816(acc3[mt][1], a[mt], b[2],  b[3]);
                mma16816(acc3[mt][2], a[mt], b2[0], b2[1]);
                mma16816(acc3[mt][3], a[mt], b2[2], b2[3]);
            }
        }
    };

    const int nK = DIM / BK;   // 32
    LDREG(0); STS(0); LDREG(1);
    __syncthreads();
    for (int k = 0; k < nK; k++) {
        int buf = k & 1;
        if (k + 1 < nK) STS(buf ^ 1);
        if (k + 2 < nK) LDREG(k + 2);
        COMPUTE(buf);
        __syncthreads();
    }

    // epilogue: silu(acc1) * acc3 -> g_h (fp16, compacted)
#pragma unroll
    for (int mt = 0; mt < 4; mt++) {
#pragma unroll
        for (int nt = 0; nt < 4; nt++) {
            int c = h0 + wn + nt * 8 + 2 * (lane & 3);
#pragma unroll
            for (int hpart = 0; hpart < 2; hpart++) {
                int r = wm + mt * 16 + (lane >> 2) + hpart * 8;
                if (m0 + r < cnt) {
                    float A0 = acc1[mt][nt][hpart * 2 + 0];
                    float A1 = acc1[mt][nt][hpart * 2 + 1];
                    float s0 = (A0 / (1.f + expf(-A0))) * acc3[mt][nt][hpart * 2 + 0];
                    float s1 = (A1 / (1.f + expf(-A1))) * acc3[mt][nt][hpart * 2 + 1];
                    *(__half2*)&g_h[((size_t)e * CAP + m0 + r) * HIDDEN + c] =
                        __floats2half2_rn(s0, s1);
                }
            }
        }
    }
}

// ------------------------------------------------------------------
// GEMM2: g_y = h W2^T   (compacted rows, weight applied later)
// grid (DIM/TN=8, CAP/TM=64, NEXP), block 256
// static smem: 2 stages x {A, B} each 128 x PAD halves = 40960 B
// ------------------------------------------------------------------
#define G2_MAT_H   (128 * PAD)
#define G2_STAGE_H (2 * G2_MAT_H)

__global__ void __launch_bounds__(256) k_ffn2(const float* __restrict__ w2) {
    int e  = blockIdx.z;
    int m0 = blockIdx.y * TM;
    int d0 = blockIdx.x * TN;
    int cnt = g_cnt[e];
    if (m0 >= cnt) return;

    __shared__ __half sm[2 * G2_STAGE_H];

    int tid = threadIdx.x;
    int wid = tid >> 5;
    int lane = tid & 31;

    // A loader (fp16 direct): idx = tid + q*256 (q<2) -> row = idx>>2, uint4-col = idx&3
    const uint4* pA[2]; uint32_t aoff[2];
#pragma unroll
    for (int q = 0; q < 2; q++) {
        int idx = tid + q * 256;
        int row = idx >> 2;
        int c   = idx & 3;
        aoff[q] = row * PAD + c * 8;
        pA[q] = (const uint4*)(g_h + ((size_t)e * CAP + m0 + row) * HIDDEN + c * 8);
    }
    // B loader (fp32 -> fp16): idx -> row = idx>>3, float4-col = idx&7
    const float* pB[4]; uint32_t boff[4];
#pragma unroll
    for (int q = 0; q < 4; q++) {
        int idx = tid + q * 256;
        int row = idx >> 3;
        int c4  = idx & 7;
        boff[q] = row * PAD + c4 * 4;
        pB[q] = w2 + ((size_t)e * DIM + d0 + row) * HIDDEN + c4 * 4;
    }

    float acc[4][4][4];
#pragma unroll
    for (int i = 0; i < 4; i++)
#pragma unroll
        for (int j = 0; j < 4; j++)
#pragma unroll
            for (int f = 0; f < 4; f++) acc[i][j][f] = 0.f;

    int wm = (wid >> 2) * 64;
    int wn = (wid & 3) * 32;
    uint32_t smb = s2u(sm);

    uint4 hA[2]; uint2 hB[4];

    auto LDREG = [&](int k) {
        int ko = k * BK;
#pragma unroll
        for (int q = 0; q < 2; q++) hA[q] = *(const uint4*)((const __half*)pA[q] + ko);
#pragma unroll
        for (int q = 0; q < 4; q++) hB[q] = f4h(*(const float4*)(pB[q] + ko));
    };
    auto STS = [&](int buf) {
        __half* st = sm + buf * G2_STAGE_H;
#pragma unroll
        for (int q = 0; q < 2; q++) *(uint4*)(st + aoff[q]) = hA[q];
#pragma unroll
        for (int q = 0; q < 4; q++) *(uint2*)(st + G2_MAT_H + boff[q]) = hB[q];
    };
    auto COMPUTE = [&](int buf) {
        uint32_t sb = smb + buf * G2_STAGE_H * 2;
        uint32_t aAddr = sb + ((wm + (lane & 15)) * PAD + (lane >> 4) * 8) * 2;
        uint32_t bRow  = (wn + ((lane >> 4) << 3) + (lane & 7)) * PAD + ((lane >> 3) & 1) * 8;
#pragma unroll
        for (int ks = 0; ks < 2; ks++) {
            uint32_t a[4][4];
#pragma unroll
            for (int mt = 0; mt < 4; mt++)
                ldm4(a[mt], aAddr + (mt * 16 * PAD + ks * 16) * 2);
            uint32_t b[4], b2[4];
            uint32_t bA = sb + G2_MAT_H * 2 + (bRow + ks * 16) * 2;
            ldm4(b,  bA);
            ldm4(b2, bA + 16 * PAD * 2);
#pragma unroll
            for (int mt = 0; mt < 4; mt++) {
                mma16816(acc[mt][0], a[mt], b[0],  b[1]);
                mma16816(acc[mt][1], a[mt], b[2],  b[3]);
                mma16816(acc[mt][2], a[mt], b2[0], b2[1]);
                mma16816(acc[mt][3], a[mt], b2[2], b2[3]);
            }
        }
    };

    const int nK = HIDDEN / BK;   // 80
    LDREG(0); STS(0); LDREG(1);
    __syncthreads();
    for (int k = 0; k < nK; k++) {
        int buf = k & 1;
        if (k + 1 < nK) STS(buf ^ 1);
        if (k + 2 < nK) LDREG(k + 2);
        COMPUTE(buf);
        __syncthreads();
    }

    // epilogue: plain store to compacted y scratch (no atomics)
#pragma unroll
    for (int mt = 0; mt < 4; mt++) {
#pragma unroll
        for (int nt = 0; nt < 4; nt++) {
            int c = d0 + wn + nt * 8 + 2 * (lane & 3);
#pragma unroll
            for (int hpart = 0; hpart < 2; hpart++) {
                int r = wm + mt * 16 + (lane >> 2) + hpart * 8;
                if (m0 + r < cnt) {
                    float2 v = make_float2(acc[mt][nt][hpart * 2 + 0],
                                           acc[mt][nt][hpart * 2 + 1]);
                    *(float2*)&g_y[((size_t)e * CAP + m0 + r) * DIM + c] = v;
                }
            }
        }
    }
}

// ---------------- combine: out[t] = w0*y[s0] + w1*y[s1] ----------------
__global__ void __launch_bounds__(256) k_comb(float* __restrict__ out) {
    int t = blockIdx.x;
    int d = threadIdx.x * 4;
    int s0 = g_slot[t * 2 + 0], s1 = g_slot[t * 2 + 1];
    float w0 = g_cw[t * 2 + 0], w1 = g_cw[t * 2 + 1];
    float4 y0 = *(const float4*)&g_y[(size_t)s0 * DIM + d];
    float4 y1 = *(const float4*)&g_y[(size_t)s1 * DIM + d];
    float4 o;
    o.x = w0 * y0.x + w1 * y1.x;
    o.y = w0 * y0.y + w1 * y1.y;
    o.z = w0 * y0.z + w1 * y1.z;
    o.w = w0 * y0.w + w1 * y1.w;
    *(float4*)&out[(size_t)t * DIM + d] = o;
}

// ---------------- launch ----------------
extern "C" void kernel_launch(void* const* d_in, const int* in_sizes, int n_in,
                              void* d_out, int out_size) {
    const float* x  = (const float*)d_in[0];
    const float* gw = (const float*)d_in[1];
    const float* w1 = (const float*)d_in[2];
    const float* w2 = (const float*)d_in[3];
    const float* w3 = (const float*)d_in[4];
    float* out = (float*)d_out;

    static int configured = 0;
    if (!configured) {
        cudaFuncSetAttribute(k_ffn1, cudaFuncAttributeMaxDynamicSharedMemorySize, G1_SMEM);
        configured = 1;
    }

    // zero output (covers any aux_loss tail element)
    cudaMemsetAsync(out, 0, (size_t)out_size * sizeof(float), 0);

    k_init<<<1, 32>>>();
    k_gate<<<(NTOK * 32) / 256, 256>>>(x, gw);

    dim3 g1(HIDDEN / TN, CAP / TM, NEXP);
    k_ffn1<<<g1, 256, G1_SMEM>>>(x, w1, w3);

    dim3 g2(DIM / TN, CAP / TM, NEXP);
    k_ffn2<<<g2, 256>>>(w2);

    k_comb<<<NTOK, 256>>>(out);
}

// round 9
// speedup vs baseline: 15.9366x; 1.4398x over previous
#include <cuda_runtime.h>
#include <cuda_fp16.h>
#include <math.h>
#include <stdint.h>

#define DIM     1024
#define HIDDEN  2560
#define NEXP    4
#define NTOK    8192
#define CAP     8192

#define TM  128
#define TN  128
#define BK  32
#define PAD 40          // halves per smem row (32 data + 8 pad) -> conflict-free ldmatrix

// ---- static scratch (no allocation allowed) ----
__device__ int    g_cnt[NEXP];
__device__ int    g_list[NEXP * CAP];
__device__ int    g_slot[NTOK * 2];
__device__ float  g_cw[NTOK * 2];
__device__ __half g_xh[(size_t)NTOK * DIM];            // fp16 x
__device__ __half g_w1h[(size_t)NEXP * HIDDEN * DIM];  // fp16 weights
__device__ __half g_w3h[(size_t)NEXP * HIDDEN * DIM];
__device__ __half g_w2h[(size_t)NEXP * DIM * HIDDEN];
__device__ __half g_h[(size_t)NEXP * CAP * HIDDEN];    // compacted SwiGLU output, fp16
__device__ float  g_y[(size_t)NEXP * CAP * DIM];       // compacted GEMM2 output, fp32

// ------------------------------------------------------------------
// helpers
// ------------------------------------------------------------------
__device__ __forceinline__ uint32_t s2u(const void* p) {
    uint32_t a;
    asm("{ .reg .u64 t; cvta.to.shared.u64 t, %1; cvt.u32.u64 %0, t; }" : "=r"(a) : "l"(p));
    return a;
}
__device__ __forceinline__ void ldm4(uint32_t (&r)[4], uint32_t addr) {
    asm volatile("ldmatrix.sync.aligned.m8n8.x4.shared.b16 {%0,%1,%2,%3}, [%4];"
                 : "=r"(r[0]), "=r"(r[1]), "=r"(r[2]), "=r"(r[3]) : "r"(addr));
}
__device__ __forceinline__ void mma16816(float (&d)[4], const uint32_t (&a)[4],
                                         uint32_t b0, uint32_t b1) {
    asm volatile("mma.sync.aligned.m16n8k16.row.col.f32.f16.f16.f32 "
                 "{%0,%1,%2,%3}, {%4,%5,%6,%7}, {%8,%9}, {%0,%1,%2,%3};"
                 : "+f"(d[0]), "+f"(d[1]), "+f"(d[2]), "+f"(d[3])
                 : "r"(a[0]), "r"(a[1]), "r"(a[2]), "r"(a[3]), "r"(b0), "r"(b1));
}
__device__ __forceinline__ uint2 f4h(float4 v) {
    __half2 lo = __floats2half2_rn(v.x, v.y);
    __half2 hi = __floats2half2_rn(v.z, v.w);
    uint2 r;
    r.x = *reinterpret_cast<uint32_t*>(&lo);
    r.y = *reinterpret_cast<uint32_t*>(&hi);
    return r;
}
__device__ __forceinline__ void cp16(uint32_t dst, const void* src, uint32_t ssz) {
    asm volatile("cp.async.cg.shared.global [%0], [%1], 16, %2;"
                 :: "r"(dst), "l"(src), "r"(ssz) : "memory");
}
#define CPCOMMIT() asm volatile("cp.async.commit_group;" ::: "memory")
#define CPWAIT(n)  asm volatile("cp.async.wait_group %0;" :: "n"(n) : "memory")

// ---------------- init / convert / gating ----------------
__global__ void k_init() {
    if (threadIdx.x < NEXP) g_cnt[threadIdx.x] = 0;
}

__global__ void __launch_bounds__(256) k_cvt(const float* __restrict__ src,
                                             __half* __restrict__ dst, int n4) {
    int i = blockIdx.x * blockDim.x + threadIdx.x;
    if (i < n4) {
        float4 v = *(const float4*)(src + (size_t)i * 4);
        *(uint2*)(dst + (size_t)i * 4) = f4h(v);
    }
}

__global__ void __launch_bounds__(256) k_gate(const float* __restrict__ x,
                                              const float* __restrict__ gw) {
    int warp = (blockIdx.x * blockDim.x + threadIdx.x) >> 5;
    int lane = threadIdx.x & 31;
    if (warp >= NTOK) return;
    const float* xr = x + (size_t)warp * DIM;

    float acc[NEXP] = {0.f, 0.f, 0.f, 0.f};
    for (int i = lane; i < DIM; i += 32) {
        float xv = xr[i];
#pragma unroll
        for (int e = 0; e < NEXP; e++) acc[e] += xv * gw[e * DIM + i];
    }
#pragma unroll
    for (int o = 16; o > 0; o >>= 1) {
#pragma unroll
        for (int e = 0; e < NEXP; e++)
            acc[e] += __shfl_xor_sync(0xffffffffu, acc[e], o);
    }
    if (lane == 0) {
        float m = acc[0];
#pragma unroll
        for (int e = 1; e < NEXP; e++) m = fmaxf(m, acc[e]);
        float p[NEXP], s = 0.f;
#pragma unroll
        for (int e = 0; e < NEXP; e++) { p[e] = expf(acc[e] - m); s += p[e]; }
        float inv_s = 1.f / s;
#pragma unroll
        for (int e = 0; e < NEXP; e++) p[e] *= inv_s;

        int i0 = 0;
#pragma unroll
        for (int e = 1; e < NEXP; e++) if (p[e] > p[i0]) i0 = e;
        int i1 = -1;
#pragma unroll
        for (int e = 0; e < NEXP; e++)
            if (e != i0 && (i1 < 0 || p[e] > p[i1])) i1 = e;

        float w0 = p[i0], w1 = p[i1];
        float inv = 1.f / (w0 + w1);
        w0 *= inv; w1 *= inv;

        int q0 = atomicAdd(&g_cnt[i0], 1);
        g_list[i0 * CAP + q0] = warp;
        g_slot[warp * 2 + 0] = i0 * CAP + q0;
        g_cw[warp * 2 + 0] = w0;
        int q1 = atomicAdd(&g_cnt[i1], 1);
        g_list[i1 * CAP + q1] = warp;
        g_slot[warp * 2 + 1] = i1 * CAP + q1;
        g_cw[warp * 2 + 1] = w1;
    }
}

// ------------------------------------------------------------------
// GEMM1: g_h = fp16( silu(Xg W1^T) * (Xg W3^T) ), cp.async 3-stage
// grid (HIDDEN/TN=20, CAP/TM=64, NEXP), block 256 (8 warps = 2M x 4N)
// ------------------------------------------------------------------
#define G1_MAT_B   (128 * PAD * 2)          // 10240 B per matrix
#define G1_STAGE_B (3 * G1_MAT_B)           // 30720 B per stage
#define G1_S       3
#define G1_SMEM    (G1_S * G1_STAGE_B)      // 92160 B

__global__ void __launch_bounds__(256) k_ffn1() {
    int e  = blockIdx.z;
    int m0 = blockIdx.y * TM;
    int h0 = blockIdx.x * TN;
    int cnt = g_cnt[e];
    if (m0 >= cnt) return;

    extern __shared__ __half sm[];
    __shared__ int rows_sh[TM];

    int tid = threadIdx.x;
    int wid = tid >> 5;
    int lane = tid & 31;
    if (tid < TM) {
        int m = m0 + tid;
        rows_sh[tid] = (m < cnt) ? g_list[e * CAP + m] : -1;
    }
    __syncthreads();

    // loader mapping: idx = tid + q*256 (q<2) -> row = idx>>2, 16B chunk = idx&3
    const __half* pA[2]; const __half* pW1[2]; const __half* pW3[2];
    uint32_t soff[2], asz[2];
#pragma unroll
    for (int q = 0; q < 2; q++) {
        int idx = tid + q * 256;
        int row = idx >> 2;
        int c   = idx & 3;                 // 16B chunk = 8 halves
        soff[q] = (row * PAD + c * 8) * 2; // byte offset in matrix
        int tok = rows_sh[row];
        asz[q] = (tok >= 0) ? 16u : 0u;
        pA[q]  = g_xh + ((tok >= 0) ? ((size_t)tok * DIM) : 0) + c * 8;
        pW1[q] = g_w1h + ((size_t)e * HIDDEN + h0 + row) * DIM + c * 8;
        pW3[q] = g_w3h + ((size_t)e * HIDDEN + h0 + row) * DIM + c * 8;
    }

    float acc1[4][4][4], acc3[4][4][4];
#pragma unroll
    for (int i = 0; i < 4; i++)
#pragma unroll
        for (int j = 0; j < 4; j++)
#pragma unroll
            for (int f = 0; f < 4; f++) { acc1[i][j][f] = 0.f; acc3[i][j][f] = 0.f; }

    int wm = (wid >> 2) * 64;
    int wn = (wid & 3) * 32;
    uint32_t smb = s2u(sm);

    auto LOAD = [&](int buf, int k) {
        uint32_t st = smb + buf * G1_STAGE_B;
        int ko = k * BK;
#pragma unroll
        for (int q = 0; q < 2; q++) {
            cp16(st + soff[q],              pA[q]  + ko, asz[q]);
            cp16(st + G1_MAT_B + soff[q],   pW1[q] + ko, 16u);
            cp16(st + 2*G1_MAT_B + soff[q], pW3[q] + ko, 16u);
        }
    };
    auto COMPUTE = [&](int buf) {
        uint32_t sb = smb + buf * G1_STAGE_B;
        uint32_t aAddr = sb + ((wm + (lane & 15)) * PAD + (lane >> 4) * 8) * 2;
        uint32_t bRow  = (wn + ((lane >> 4) << 3) + (lane & 7)) * PAD + ((lane >> 3) & 1) * 8;
#pragma unroll
        for (int ks = 0; ks < 2; ks++) {
            uint32_t a[4][4];
#pragma unroll
            for (int mt = 0; mt < 4; mt++)
                ldm4(a[mt], aAddr + (mt * 16 * PAD + ks * 16) * 2);
            uint32_t b[4], b2[4];
            uint32_t bA = sb + G1_MAT_B + (bRow + ks * 16) * 2;
            ldm4(b,  bA);
            ldm4(b2, bA + 16 * PAD * 2);
#pragma unroll
            for (int mt = 0; mt < 4; mt++) {
                mma16816(acc1[mt][0], a[mt], b[0],  b[1]);
                mma16816(acc1[mt][1], a[mt], b[2],  b[3]);
                mma16816(acc1[mt][2], a[mt], b2[0], b2[1]);
                mma16816(acc1[mt][3], a[mt], b2[2], b2[3]);
            }
            uint32_t cA = sb + 2 * G1_MAT_B + (bRow + ks * 16) * 2;
            ldm4(b,  cA);
            ldm4(b2, cA + 16 * PAD * 2);
#pragma unroll
            for (int mt = 0; mt < 4; mt++) {
                mma16816(acc3[mt][0], a[mt], b[0],  b[1]);
                mma16816(acc3[mt][1], a[mt], b[2],  b[3]);
                mma16816(acc3[mt][2], a[mt], b2[0], b2[1]);
                mma16816(acc3[mt][3], a[mt], b2[2], b2[3]);
            }
        }
    };

    const int nK = DIM / BK;   // 32
#pragma unroll
    for (int s = 0; s < G1_S - 1; s++) { LOAD(s, s); CPCOMMIT(); }
    for (int k = 0; k < nK; k++) {
        CPWAIT(G1_S - 2);
        __syncthreads();
        COMPUTE(k % G1_S);
        int kn = k + G1_S - 1;
        if (kn < nK) LOAD(kn % G1_S, kn);
        CPCOMMIT();
    }

    // epilogue: silu(acc1) * acc3 -> g_h (fp16, compacted)
#pragma unroll
    for (int mt = 0; mt < 4; mt++) {
#pragma unroll
        for (int nt = 0; nt < 4; nt++) {
            int c = h0 + wn + nt * 8 + 2 * (lane & 3);
#pragma unroll
            for (int hpart = 0; hpart < 2; hpart++) {
                int r = wm + mt * 16 + (lane >> 2) + hpart * 8;
                if (m0 + r < cnt) {
                    float A0 = acc1[mt][nt][hpart * 2 + 0];
                    float A1 = acc1[mt][nt][hpart * 2 + 1];
                    float s0 = (A0 / (1.f + expf(-A0))) * acc3[mt][nt][hpart * 2 + 0];
                    float s1 = (A1 / (1.f + expf(-A1))) * acc3[mt][nt][hpart * 2 + 1];
                    *(__half2*)&g_h[((size_t)e * CAP + m0 + r) * HIDDEN + c] =
                        __floats2half2_rn(s0, s1);
                }
            }
        }
    }
}

// ------------------------------------------------------------------
// GEMM2: g_y = h W2^T  (compacted rows), cp.async 4-stage
// grid (DIM/TN=8, CAP/TM=64, NEXP), block 256
// ------------------------------------------------------------------
#define G2_MAT_B   (128 * PAD * 2)          // 10240 B
#define G2_STAGE_B (2 * G2_MAT_B)           // 20480 B
#define G2_S       4
#define G2_SMEM    (G2_S * G2_STAGE_B)      // 81920 B

__global__ void __launch_bounds__(256) k_ffn2() {
    int e  = blockIdx.z;
    int m0 = blockIdx.y * TM;
    int d0 = blockIdx.x * TN;
    int cnt = g_cnt[e];
    if (m0 >= cnt) return;

    extern __shared__ __half sm[];

    int tid = threadIdx.x;
    int wid = tid >> 5;
    int lane = tid & 31;

    const __half* pA[2]; const __half* pB[2];
    uint32_t soff[2], asz[2];
#pragma unroll
    for (int q = 0; q < 2; q++) {
        int idx = tid + q * 256;
        int row = idx >> 2;
        int c   = idx & 3;
        soff[q] = (row * PAD + c * 8) * 2;
        bool ok = (m0 + row) < cnt;
        asz[q] = ok ? 16u : 0u;
        pA[q] = g_h + ((size_t)e * CAP + m0 + (ok ? row : 0)) * HIDDEN + c * 8;
        pB[q] = g_w2h + ((size_t)e * DIM + d0 + row) * HIDDEN + c * 8;
    }

    float acc[4][4][4];
#pragma unroll
    for (int i = 0; i < 4; i++)
#pragma unroll
        for (int j = 0; j < 4; j++)
#pragma unroll
            for (int f = 0; f < 4; f++) acc[i][j][f] = 0.f;

    int wm = (wid >> 2) * 64;
    int wn = (wid & 3) * 32;
    uint32_t smb = s2u(sm);

    auto LOAD = [&](int buf, int k) {
        uint32_t st = smb + buf * G2_STAGE_B;
        int ko = k * BK;
#pragma unroll
        for (int q = 0; q < 2; q++) {
            cp16(st + soff[q],            pA[q] + ko, asz[q]);
            cp16(st + G2_MAT_B + soff[q], pB[q] + ko, 16u);
        }
    };
    auto COMPUTE = [&](int buf) {
        uint32_t sb = smb + buf * G2_STAGE_B;
        uint32_t aAddr = sb + ((wm + (lane & 15)) * PAD + (lane >> 4) * 8) * 2;
        uint32_t bRow  = (wn + ((lane >> 4) << 3) + (lane & 7)) * PAD + ((lane >> 3) & 1) * 8;
#pragma unroll
        for (int ks = 0; ks < 2; ks++) {
            uint32_t a[4][4];
#pragma unroll
            for (int mt = 0; mt < 4; mt++)
                ldm4(a[mt], aAddr + (mt * 16 * PAD + ks * 16) * 2);
            uint32_t b[4], b2[4];
            uint32_t bA = sb + G2_MAT_B + (bRow + ks * 16) * 2;
            ldm4(b,  bA);
            ldm4(b2, bA + 16 * PAD * 2);
#pragma unroll
            for (int mt = 0; mt < 4; mt++) {
                mma16816(acc[mt][0], a[mt], b[0],  b[1]);
                mma16816(acc[mt][1], a[mt], b[2],  b[3]);
                mma16816(acc[mt][2], a[mt], b2[0], b2[1]);
                mma16816(acc[mt][3], a[mt], b2[2], b2[3]);
            }
        }
    };

    const int nK = HIDDEN / BK;   // 80
#pragma unroll
    for (int s = 0; s < G2_S - 1; s++) { LOAD(s, s); CPCOMMIT(); }
    for (int k = 0; k < nK; k++) {
        CPWAIT(G2_S - 2);
        __syncthreads();
        COMPUTE(k % G2_S);
        int kn = k + G2_S - 1;
        if (kn < nK) LOAD(kn % G2_S, kn);
        CPCOMMIT();
    }

    // epilogue: plain store to compacted y scratch (no atomics)
#pragma unroll
    for (int mt = 0; mt < 4; mt++) {
#pragma unroll
        for (int nt = 0; nt < 4; nt++) {
            int c = d0 + wn + nt * 8 + 2 * (lane & 3);
#pragma unroll
            for (int hpart = 0; hpart < 2; hpart++) {
                int r = wm + mt * 16 + (lane >> 2) + hpart * 8;
                if (m0 + r < cnt) {
                    float2 v = make_float2(acc[mt][nt][hpart * 2 + 0],
                                           acc[mt][nt][hpart * 2 + 1]);
                    *(float2*)&g_y[((size_t)e * CAP + m0 + r) * DIM + c] = v;
                }
            }
        }
    }
}

// ---------------- combine: out[t] = w0*y[s0] + w1*y[s1] ----------------
__global__ void __launch_bounds__(256) k_comb(float* __restrict__ out) {
    int t = blockIdx.x;
    int d = threadIdx.x * 4;
    int s0 = g_slot[t * 2 + 0], s1 = g_slot[t * 2 + 1];
    float w0 = g_cw[t * 2 + 0], w1 = g_cw[t * 2 + 1];
    float4 y0 = *(const float4*)&g_y[(size_t)s0 * DIM + d];
    float4 y1 = *(const float4*)&g_y[(size_t)s1 * DIM + d];
    float4 o;
    o.x = w0 * y0.x + w1 * y1.x;
    o.y = w0 * y0.y + w1 * y1.y;
    o.z = w0 * y0.z + w1 * y1.z;
    o.w = w0 * y0.w + w1 * y1.w;
    *(float4*)&out[(size_t)t * DIM + d] = o;
}

// ---------------- launch ----------------
extern "C" void kernel_launch(void* const* d_in, const int* in_sizes, int n_in,
                              void* d_out, int out_size) {
    const float* x  = (const float*)d_in[0];
    const float* gw = (const float*)d_in[1];
    const float* w1 = (const float*)d_in[2];
    const float* w2 = (const float*)d_in[3];
    const float* w3 = (const float*)d_in[4];
    float* out = (float*)d_out;

    static int configured = 0;
    if (!configured) {
        cudaFuncSetAttribute(k_ffn1, cudaFuncAttributeMaxDynamicSharedMemorySize, G1_SMEM);
        cudaFuncSetAttribute(k_ffn2, cudaFuncAttributeMaxDynamicSharedMemorySize, G2_SMEM);
        configured = 1;
    }

    cudaMemsetAsync(out, 0, (size_t)out_size * sizeof(float), 0);

    k_init<<<1, 32>>>();

    // fp32 -> fp16 conversions (x + all weights)
    {
        __half* dxh;  cudaGetSymbolAddress((void**)&dxh,  g_xh);
        __half* dw1h; cudaGetSymbolAddress((void**)&dw1h, g_w1h);
        __half* dw3h; cudaGetSymbolAddress((void**)&dw3h, g_w3h);
        __half* dw2h; cudaGetSymbolAddress((void**)&dw2h, g_w2h);
        int nx = NTOK * DIM / 4;
        int nw = NEXP * HIDDEN * DIM / 4;
        k_cvt<<<(nx + 255) / 256, 256>>>(x,  dxh,  nx);
        k_cvt<<<(nw + 255) / 256, 256>>>(w1, dw1h, nw);
        k_cvt<<<(nw + 255) / 256, 256>>>(w3, dw3h, nw);
        k_cvt<<<(nw + 255) / 256, 256>>>(w2, dw2h, nw);
    }

    k_gate<<<(NTOK * 32) / 256, 256>>>(x, gw);

    dim3 g1(HIDDEN / TN, CAP / TM, NEXP);
    k_ffn1<<<g1, 256, G1_SMEM>>>();

    dim3 g2(DIM / TN, CAP / TM, NEXP);
    k_ffn2<<<g2, 256, G2_SMEM>>>();

    k_comb<<<NTOK, 256>>>(out);
}